// round 8
// baseline (speedup 1.0000x reference)
#include <cuda_runtime.h>
#include <math.h>
#include <float.h>

#define H 1024
#define TWO_H 2048
#define S_LEN 2048
#define D_EMB 512
#define L_CLS 16
#define VOCAB 50257
#define OUT_IN 1552    // H + L + D
#define COMB_IN 2576   // D + 2H + L
#define CONST_N 528    // L + D
#define CONST_N4 132

#define NB 144
#define CHAIN_NB 64
#define HELP_NB (NB - CHAIN_NB)   // 80
#define NTHREADS 1024

// ---------------- scratch (device globals; no allocation) ----------------
__device__ __align__(16) float g_vpart[32 * 2048];
__device__ __align__(16) float g_ctxpart[64 * 2048];  // per-chain-block unnormalized ctx
__device__ __align__(16) float g_scores[2048];        // raw score logits
__device__ float g_am[CHAIN_NB], g_as[CHAIN_NB];      // per-block (max, expsum)
__device__ __align__(16) float g_x1[1024];
__device__ __align__(16) float g_x2[1024];
__device__ __align__(16) float g_x3[1024];
__device__ __align__(16) float g_gh[3072];
__device__ __align__(16) float g_gi[3072];
__device__ __align__(16) float g_hn[1024];
__device__ float g_pm[NB], g_ps[NB];
__device__ unsigned g_wq;      // const-part chunk queue
__device__ unsigned g_wq2;     // phase-F chunk queue
__device__ unsigned g_ghcnt;   // helper gh-done counter

// ---------------- grid barriers ----------------
#define NBAR 8
__device__ unsigned g_cnt[NBAR];
__device__ volatile unsigned g_gen[NBAR];

__device__ __forceinline__ void gbar(int id, int n) {
    __syncthreads();
    if (threadIdx.x == 0) {
        __threadfence();
        unsigned g = g_gen[id];
        if (atomicAdd(&g_cnt[id], 1u) == (unsigned)(n - 1)) {
            g_cnt[id] = 0;
            __threadfence();
            g_gen[id] = g + 1;
        } else {
            while (g_gen[id] == g) __nanosleep(32);
        }
        __threadfence();
    }
    __syncthreads();
}

// ---------------- compile-time-unrolled warp dots ----------------
template<int N4>
__device__ __forceinline__ float wdot(const float4* __restrict__ wr,
                                      const float4* __restrict__ xs, int lane) {
    float acc = 0.f;
    constexpr int FULL = N4 / 32;
#pragma unroll 4
    for (int k = 0; k < FULL; k++) {
        int i = lane + k * 32;
        float4 a = wr[i], b = xs[i];
        acc += a.x * b.x + a.y * b.y + a.z * b.z + a.w * b.w;
    }
    if constexpr (N4 % 32 != 0) {
        int i = lane + FULL * 32;
        if (i < N4) {
            float4 a = wr[i], b = xs[i];
            acc += a.x * b.x + a.y * b.y + a.z * b.z + a.w * b.w;
        }
    }
#pragma unroll
    for (int o = 16; o; o >>= 1) acc += __shfl_xor_sync(0xffffffffu, acc, o);
    return acc;
}

template<int N4>
__device__ __forceinline__ float wdot_s(const float4* __restrict__ wr,
                                        const float4* __restrict__ xs, int lane) {
    float acc = 0.f;
    constexpr int FULL = N4 / 32;
#pragma unroll 4
    for (int k = 0; k < FULL; k++) {
        int i = lane + k * 32;
        float4 a = __ldcs(wr + i); float4 b = xs[i];
        acc += a.x * b.x + a.y * b.y + a.z * b.z + a.w * b.w;
    }
    if constexpr (N4 % 32 != 0) {
        int i = lane + FULL * 32;
        if (i < N4) {
            float4 a = __ldcs(wr + i); float4 b = xs[i];
            acc += a.x * b.x + a.y * b.y + a.z * b.z + a.w * b.w;
        }
    }
#pragma unroll
    for (int o = 16; o; o >>= 1) acc += __shfl_xor_sync(0xffffffffu, acc, o);
    return acc;
}

template<int N4>
__device__ __forceinline__ void quad_dot_s(const float4* __restrict__ W0,
                                           const float4* __restrict__ W1,
                                           const float4* __restrict__ W2,
                                           const float4* __restrict__ W3,
                                           const float4* __restrict__ xs, int lane,
                                           float& a0, float& a1, float& a2, float& a3) {
    a0 = a1 = a2 = a3 = 0.f;
    constexpr int FULL = N4 / 32;
#pragma unroll 2
    for (int k = 0; k < FULL; k++) {
        int i = lane + k * 32;
        float4 x = xs[i];
        float4 q0 = __ldcs(W0 + i), q1 = __ldcs(W1 + i);
        float4 q2 = __ldcs(W2 + i), q3 = __ldcs(W3 + i);
        a0 += q0.x * x.x + q0.y * x.y + q0.z * x.z + q0.w * x.w;
        a1 += q1.x * x.x + q1.y * x.y + q1.z * x.z + q1.w * x.w;
        a2 += q2.x * x.x + q2.y * x.y + q2.z * x.z + q2.w * x.w;
        a3 += q3.x * x.x + q3.y * x.y + q3.z * x.z + q3.w * x.w;
    }
    if constexpr (N4 % 32 != 0) {
        int i = lane + FULL * 32;
        if (i < N4) {
            float4 x = xs[i];
            float4 q0 = __ldcs(W0 + i), q1 = __ldcs(W1 + i);
            float4 q2 = __ldcs(W2 + i), q3 = __ldcs(W3 + i);
            a0 += q0.x * x.x + q0.y * x.y + q0.z * x.z + q0.w * x.w;
            a1 += q1.x * x.x + q1.y * x.y + q1.z * x.z + q1.w * x.w;
            a2 += q2.x * x.x + q2.y * x.y + q2.z * x.z + q2.w * x.w;
            a3 += q3.x * x.x + q3.y * x.y + q3.z * x.z + q3.w * x.w;
        }
    }
#pragma unroll
    for (int o = 16; o; o >>= 1) {
        a0 += __shfl_xor_sync(0xffffffffu, a0, o);
        a1 += __shfl_xor_sync(0xffffffffu, a1, o);
        a2 += __shfl_xor_sync(0xffffffffu, a2, o);
        a3 += __shfl_xor_sync(0xffffffffu, a3, o);
    }
}

// --------------------------------------------------------------------------
__global__ void __launch_bounds__(NTHREADS, 1) fused_decoder(
    const int* __restrict__ tok, const float* __restrict__ hid,
    const float* __restrict__ enc, const float* __restrict__ nlg,
    const float* __restrict__ emb, const float* __restrict__ attn_W,
    const float* __restrict__ comb_W, const float* __restrict__ comb_b,
    const float* __restrict__ fc1_W, const float* __restrict__ fc1_b,
    const float* __restrict__ fc2_W, const float* __restrict__ fc2_b,
    const float* __restrict__ Wih, const float* __restrict__ Whh,
    const float* __restrict__ bih, const float* __restrict__ bhh,
    const float* __restrict__ out_W, const float* __restrict__ out_b,
    float* __restrict__ out)
{
    __shared__ __align__(16) float sx[2608];
    __shared__ float sr[64];
    __shared__ float se[32];
    __shared__ float swc[64];
    __shared__ float sp[32];
    __shared__ int sc_chunk;
    const int b = blockIdx.x, tid = threadIdx.x;
    const int w = tid >> 5, lane = tid & 31;

    if (b < CHAIN_NB) {
        // ======================= CHAIN (64 blocks) =========================
        // S0: v-partials: 32 k-chunks (32 rows of attn_W; H=1024 total)
        //     x 2 column halves -> 64 blocks
        {
            int kc = b >> 1, half = b & 1;
            if (tid < 32) sx[tid] = hid[kc * 32 + tid];
            __syncthreads();
            int col = half * 1024 + tid;
            const float* Wp = attn_W + (size_t)(kc * 32) * TWO_H + col;
            float acc = 0.f;
#pragma unroll 8
            for (int kk = 0; kk < 32; ++kk)
                acc = fmaf(Wp[(size_t)kk * TWO_H], sx[kk], acc);
            g_vpart[kc * 2048 + col] = acc;
        }
        gbar(0, CHAIN_NB);

        // S1-FUSED: scores + block-local softmax stats + unnormalized ctx,
        //           single pass over enc (32 rows per block)
        {
            __syncthreads();
            // v = sum of 32 partials -> sx[0..2047]
            for (int i = tid; i < 2048; i += NTHREADS) {
                float s = 0.f;
#pragma unroll
                for (int k = 0; k < 32; k++) s += g_vpart[k * 2048 + i];
                sx[i] = s;
            }
            __syncthreads();
            // warp w -> row b*32 + w   (64 blocks x 32 warps = 2048 rows)
            int row = b * 32 + w;
            float l = wdot<TWO_H / 4>((const float4*)(enc + (size_t)row * TWO_H),
                                      (const float4*)sx, lane);
            if (lane == 0) { g_scores[row] = l; sr[w] = l; }
            __syncthreads();
            // block max
            if (tid == 0) {
                float v = sr[0];
                for (int k = 1; k < 32; k++) v = fmaxf(v, sr[k]);
                sr[32] = v;
            }
            __syncthreads();
            float m_b = sr[32];
            // per-row weights e_s = exp(l_s - m_b)
            if (tid < 32) se[tid] = expf(sr[tid] - m_b);
            __syncthreads();
            // block expsum
            if (tid == 0) {
                float s = 0.f;
                for (int k = 0; k < 32; k++) s += se[k];
                g_am[b] = m_b; g_as[b] = s;
            }
            // unnormalized ctx_b[j] = sum_s e_s * enc[row_s, j]
            // thread tid owns cols {tid, tid+1024}; rows re-read (L2-hot)
            float c0 = 0.f, c1 = 0.f;
            const float* Eb = enc + (size_t)(b * 32) * TWO_H;
#pragma unroll 8
            for (int s = 0; s < 32; s++) {
                float ws = se[s];
                c0 = fmaf(ws, Eb[(size_t)s * TWO_H + tid], c0);
                c1 = fmaf(ws, Eb[(size_t)s * TWO_H + 1024 + tid], c1);
            }
            g_ctxpart[(size_t)b * 2048 + tid] = c0;
            g_ctxpart[(size_t)b * 2048 + 1024 + tid] = c1;
        }
        gbar(1, CHAIN_NB);

        // S2: comb — combine ctx partials (split-softmax algebra) + GEMV
        {
            __syncthreads();
            // every thread: global M, Z from the 64 (m,S) pairs (broadcast loads)
            float M = -FLT_MAX;
#pragma unroll
            for (int k = 0; k < CHAIN_NB; k++) M = fmaxf(M, g_am[k]);
            float Z = 0.f;
#pragma unroll
            for (int k = 0; k < CHAIN_NB; k++) Z += g_as[k] * expf(g_am[k] - M);
            float invZ = 1.f / Z;
            if (tid < CHAIN_NB) swc[tid] = expf(g_am[tid] - M) * invZ;
            __syncthreads();
            // attention-weights output (block 0)
            if (b == 0) {
                out[VOCAB + H + tid]        = expf(g_scores[tid] - M) * invZ;
                out[VOCAB + H + 1024 + tid] = expf(g_scores[tid + 1024] - M) * invZ;
            }
            int t = *tok;
            for (int i = tid; i < COMB_IN; i += NTHREADS) {
                float v;
                if (i < D_EMB) v = emb[(size_t)t * D_EMB + i];
                else if (i < D_EMB + TWO_H) {
                    int c = i - D_EMB; float s = 0.f;
#pragma unroll
                    for (int k = 0; k < CHAIN_NB; k++)
                        s = fmaf(swc[k], g_ctxpart[(size_t)k * 2048 + c], s);
                    v = s;
                } else v = nlg[i - (D_EMB + TWO_H)];
                sx[i] = v;
            }
            __syncthreads();
            int row = b * 16 + (w >> 1), half = w & 1;
            float part = wdot<COMB_IN / 8>(
                (const float4*)(comb_W + (size_t)row * COMB_IN + half * (COMB_IN / 2)),
                (const float4*)(sx + half * (COMB_IN / 2)), lane);
            if (lane == 0) sp[w] = part;
            __syncthreads();
            if (tid < 16) {
                int r = b * 16 + tid;
                g_x1[r] = fmaxf(sp[2 * tid] + sp[2 * tid + 1] + comb_b[r], 0.f);
            }
        }
        gbar(2, CHAIN_NB);

        // S3: fc1 — 64 blocks, 16 rows, 2-warp split
        {
            for (int i = tid; i < H; i += NTHREADS) sx[i] = g_x1[i];
            __syncthreads();
            int row = b * 16 + (w >> 1), half = w & 1;
            float part = wdot<H / 8>(
                (const float4*)(fc1_W + (size_t)row * H + half * (H / 2)),
                (const float4*)(sx + half * (H / 2)), lane);
            if (lane == 0) sp[w] = part;
            __syncthreads();
            if (tid < 16) {
                int r = b * 16 + tid;
                g_x2[r] = fmaxf(sp[2 * tid] + sp[2 * tid + 1] + fc1_b[r], 0.f);
            }
        }
        gbar(3, CHAIN_NB);

        // S4: fc2
        {
            for (int i = tid; i < H; i += NTHREADS) sx[i] = g_x2[i];
            __syncthreads();
            int row = b * 16 + (w >> 1), half = w & 1;
            float part = wdot<H / 8>(
                (const float4*)(fc2_W + (size_t)row * H + half * (H / 2)),
                (const float4*)(sx + half * (H / 2)), lane);
            if (lane == 0) sp[w] = part;
            __syncthreads();
            if (tid < 16) {
                int r = b * 16 + tid;
                g_x3[r] = fmaxf(sp[2 * tid] + sp[2 * tid + 1] + fc2_b[r], 0.f);
            }
        }
        gbar(4, CHAIN_NB);

        // S5: gi = Wih . x3 + bih  (64 blocks, 3072 rows)
        {
            for (int i = tid; i < H; i += NTHREADS) sx[i] = g_x3[i];
            __syncthreads();
            int gw2 = b * 32 + w;
            for (int r = gw2; r < 3072; r += 2048) {
                float acc = wdot<H / 4>((const float4*)(Wih + (size_t)r * H),
                                        (const float4*)sx, lane);
                if (lane == 0) g_gi[r] = acc + bih[r];
            }
        }
        gbar(5, CHAIN_NB);

        // S6: GRU gates (block 0; gh produced by helpers, flag-synced)
        if (b == 0) {
            if (tid == 0) {
                while (*(volatile unsigned*)&g_ghcnt < (unsigned)HELP_NB) __nanosleep(32);
                __threadfence();
            }
            __syncthreads();
            float r = 1.f / (1.f + expf(-(g_gi[tid] + g_gh[tid])));
            float z = 1.f / (1.f + expf(-(g_gi[H + tid] + g_gh[H + tid])));
            float n = tanhf(g_gi[2 * H + tid] + r * g_gh[2 * H + tid]);
            float hn = (1.f - z) * n + z * hid[tid];
            g_hn[tid] = hn;
            out[VOCAB + tid] = hn;
        }
    } else {
        // ============ HELPERS (80 blocks): gh = Whh.h + bhh ================
        for (int i = tid; i < H; i += NTHREADS) sx[i] = hid[i];
        __syncthreads();
        int gw = (b - CHAIN_NB) * 32 + w;   // [0, 2560)
        {
            float acc = wdot<H / 4>((const float4*)(Whh + (size_t)gw * H),
                                    (const float4*)sx, lane);
            if (lane == 0) g_gh[gw] = acc + bhh[gw];
        }
        if (gw < 512) {
            int r2 = gw + 2560;             // rows [2560, 3072)
            float acc = wdot<H / 4>((const float4*)(Whh + (size_t)r2 * H),
                                    (const float4*)sx, lane);
            if (lane == 0) g_gh[r2] = acc + bhh[r2];
        }
        __syncthreads();
        if (tid == 0) { __threadfence(); atomicAdd(&g_ghcnt, 1u); }
    }

    // ============ ALL BLOCKS: const logits via work stealing ===============
    // out[r] = out_b[r] + out_W[r, 1024:1552] . [nlg, emb]
    {
        int t = *tok;
        __syncthreads();
        for (int i = tid; i < CONST_N; i += NTHREADS)
            sx[i] = (i < L_CLS) ? nlg[i] : emb[(size_t)t * D_EMB + (i - L_CLS)];
        __syncthreads();
        for (;;) {
            if (tid == 0) sc_chunk = (int)atomicAdd(&g_wq, 1u);
            __syncthreads();
            int c = sc_chunk;
            __syncthreads();
            if (c * 128 >= VOCAB) break;
            int r0 = c * 128 + w * 4;
            if (r0 >= VOCAB) continue;
            const float* base = out_W + (size_t)r0 * OUT_IN + H;
            if (r0 + 3 < VOCAB) {
                float a0, a1, a2, a3;
                quad_dot_s<CONST_N4>((const float4*)base,
                                     (const float4*)(base + OUT_IN),
                                     (const float4*)(base + 2 * OUT_IN),
                                     (const float4*)(base + 3 * OUT_IN),
                                     (const float4*)sx, lane, a0, a1, a2, a3);
                if (lane < 4) {
                    float acc = (lane == 0) ? a0 : (lane == 1) ? a1 : (lane == 2) ? a2 : a3;
                    out[r0 + lane] = acc + out_b[r0 + lane];
                }
            } else {
                for (int j = 0; j < 4; j++) {
                    int r = r0 + j;
                    if (r >= VOCAB) break;
                    float acc = wdot_s<CONST_N4>((const float4*)(out_W + (size_t)r * OUT_IN + H),
                                                 (const float4*)sx, lane);
                    if (lane == 0) out[r] = acc + out_b[r];
                }
            }
        }
    }

    // ============== FULL GRID: h_new logits + lse (work-stolen) ============
    gbar(6, NB);
    if (b == 0 && tid == 0) { g_wq = 0; g_ghcnt = 0; }  // reset for next replay
    {
        for (int i = tid; i < H; i += NTHREADS) sx[i] = g_hn[i];
        __syncthreads();
        float m = -FLT_MAX, ssum = 0.f;
        for (;;) {
            if (tid == 0) sc_chunk = (int)atomicAdd(&g_wq2, 1u);
            __syncthreads();
            int c = sc_chunk;
            __syncthreads();
            if (c * 128 >= VOCAB) break;
            int r0 = c * 128 + w * 4;
            if (r0 >= VOCAB) continue;
            const float* base = out_W + (size_t)r0 * OUT_IN;
            if (r0 + 3 < VOCAB) {
                float a0, a1, a2, a3;
                quad_dot_s<H / 4>((const float4*)base,
                                  (const float4*)(base + OUT_IN),
                                  (const float4*)(base + 2 * OUT_IN),
                                  (const float4*)(base + 3 * OUT_IN),
                                  (const float4*)sx, lane, a0, a1, a2, a3);
                if (lane < 4) {
                    float acc = (lane == 0) ? a0 : (lane == 1) ? a1 : (lane == 2) ? a2 : a3;
                    int r = r0 + lane;
                    float z = out[r] + acc;
                    out[r] = z;
                    if (z > m) { ssum = ssum * expf(m - z) + 1.f; m = z; }
                    else       { ssum += expf(z - m); }
                }
            } else {
                for (int j = 0; j < 4; j++) {
                    int r = r0 + j;
                    if (r >= VOCAB) break;
                    float acc = wdot_s<H / 4>((const float4*)(out_W + (size_t)r * OUT_IN),
                                              (const float4*)sx, lane);
                    if (lane == j) {
                        float z = out[r] + acc;
                        out[r] = z;
                        if (z > m) { ssum = ssum * expf(m - z) + 1.f; m = z; }
                        else       { ssum += expf(z - m); }
                    }
                }
            }
        }
        // merge (m, ssum) across lanes
#pragma unroll
        for (int o = 16; o; o >>= 1) {
            float mo = __shfl_xor_sync(0xffffffffu, m, o);
            float so = __shfl_xor_sync(0xffffffffu, ssum, o);
            float nm = fmaxf(m, mo);
            ssum = ssum * expf(m - nm) + so * expf(mo - nm);
            m = nm;
        }
        if (lane == 0) { sr[w] = m; sr[32 + w] = ssum; }
        __syncthreads();
        if (tid == 0) {
            float M = -FLT_MAX;
            for (int k = 0; k < 32; k++) M = fmaxf(M, sr[k]);
            float S = 0.f;
            for (int k = 0; k < 32; k++) S += sr[32 + k] * expf(sr[k] - M);
            g_pm[b] = M; g_ps[b] = S;
        }
    }
    gbar(7, NB);
    if (b == 0 && tid == 0) g_wq2 = 0;  // reset for next replay
    // every block computes logZ redundantly (saves one full-grid barrier)
    {
        if (w == 0) {
            float m = -FLT_MAX, s = 0.f;
            for (int i = lane; i < NB; i += 32) {
                float mi = g_pm[i], si = g_ps[i];
                float nm = fmaxf(m, mi);
                s = s * expf(m - nm) + si * expf(mi - nm);
                m = nm;
            }
#pragma unroll
            for (int o = 16; o; o >>= 1) {
                float mo = __shfl_xor_sync(0xffffffffu, m, o);
                float so = __shfl_xor_sync(0xffffffffu, s, o);
                float nm = fmaxf(m, mo);
                s = s * expf(m - nm) + so * expf(mo - nm);
                m = nm;
            }
            if (lane == 0) sr[0] = m + logf(s);
        }
        __syncthreads();
        float lz = sr[0];
        int i = b * NTHREADS + tid;
        if (i < VOCAB) out[i] -= lz;
    }
}

// --------------------------------------------------------------------------
extern "C" void kernel_launch(void* const* d_in, const int* in_sizes, int n_in,
                              void* d_out, int out_size) {
    const int*   tok    = (const int*)d_in[0];
    const float* hid    = (const float*)d_in[1];
    const float* enc    = (const float*)d_in[2];
    const float* nlg    = (const float*)d_in[3];
    const float* emb    = (const float*)d_in[4];
    const float* attn_W = (const float*)d_in[5];
    // d_in[6] = attn_b: softmax-invariant, drops out by construction
    const float* comb_W = (const float*)d_in[7];
    const float* comb_b = (const float*)d_in[8];
    const float* fc1_W  = (const float*)d_in[9];
    const float* fc1_b  = (const float*)d_in[10];
    const float* fc2_W  = (const float*)d_in[11];
    const float* fc2_b  = (const float*)d_in[12];
    const float* Wih    = (const float*)d_in[13];
    const float* Whh    = (const float*)d_in[14];
    const float* bih    = (const float*)d_in[15];
    const float* bhh    = (const float*)d_in[16];
    const float* out_W  = (const float*)d_in[17];
    const float* out_b  = (const float*)d_in[18];
    float* out = (float*)d_out;

    fused_decoder<<<NB, NTHREADS>>>(tok, hid, enc, nlg, emb, attn_W,
                                    comb_W, comb_b, fc1_W, fc1_b, fc2_W, fc2_b,
                                    Wih, Whh, bih, bhh, out_W, out_b, out);
}

// round 9
// speedup vs baseline: 1.1724x; 1.1724x over previous
#include <cuda_runtime.h>
#include <math.h>
#include <float.h>

#define H 1024
#define TWO_H 2048
#define S_LEN 2048
#define D_EMB 512
#define L_CLS 16
#define VOCAB 50257
#define OUT_IN 1552    // H + L + D
#define COMB_IN 2576   // D + 2H + L
#define CONST_N 528    // L + D
#define CONST_N4 132

#define NB 144
#define CHAIN_NB 64
#define HELP_NB (NB - CHAIN_NB)   // 80
#define NTHREADS 1024

// ---------------- scratch (device globals; no allocation) ----------------
__device__ __align__(16) float g_vpart[32 * 2048];
__device__ __align__(16) float g_ctxpart[32 * 2048];
__device__ __align__(16) float g_scores[2048];
__device__ __align__(16) float g_x1[1024];
__device__ __align__(16) float g_x2[1024];
__device__ __align__(16) float g_x3[1024];
__device__ __align__(16) float g_gh[3072];
__device__ __align__(16) float g_gi[3072];
__device__ float g_pm[NB], g_ps[NB];
__device__ unsigned g_wq;      // const-part chunk queue
__device__ unsigned g_wq2;     // phase-F chunk queue

// ---------------- grid barriers ----------------
#define NBAR 8
__device__ unsigned g_cnt[NBAR];
__device__ volatile unsigned g_gen[NBAR];

__device__ __forceinline__ void gbar(int id, int n) {
    __syncthreads();
    if (threadIdx.x == 0) {
        __threadfence();
        unsigned g = g_gen[id];
        if (atomicAdd(&g_cnt[id], 1u) == (unsigned)(n - 1)) {
            g_cnt[id] = 0;
            __threadfence();
            g_gen[id] = g + 1;
        } else {
            while (g_gen[id] == g) __nanosleep(32);
        }
        __threadfence();
    }
    __syncthreads();
}

// ---------------- compile-time-unrolled warp dots ----------------
template<int N4>
__device__ __forceinline__ float wdot(const float4* __restrict__ wr,
                                      const float4* __restrict__ xs, int lane) {
    float acc = 0.f;
    constexpr int FULL = N4 / 32;
#pragma unroll 4
    for (int k = 0; k < FULL; k++) {
        int i = lane + k * 32;
        float4 a = wr[i], b = xs[i];
        acc += a.x * b.x + a.y * b.y + a.z * b.z + a.w * b.w;
    }
    if constexpr (N4 % 32 != 0) {
        int i = lane + FULL * 32;
        if (i < N4) {
            float4 a = wr[i], b = xs[i];
            acc += a.x * b.x + a.y * b.y + a.z * b.z + a.w * b.w;
        }
    }
#pragma unroll
    for (int o = 16; o; o >>= 1) acc += __shfl_xor_sync(0xffffffffu, acc, o);
    return acc;
}

template<int N4>
__device__ __forceinline__ float wdot_s(const float4* __restrict__ wr,
                                        const float4* __restrict__ xs, int lane) {
    float acc = 0.f;
    constexpr int FULL = N4 / 32;
#pragma unroll 4
    for (int k = 0; k < FULL; k++) {
        int i = lane + k * 32;
        float4 a = __ldcs(wr + i); float4 b = xs[i];
        acc += a.x * b.x + a.y * b.y + a.z * b.z + a.w * b.w;
    }
    if constexpr (N4 % 32 != 0) {
        int i = lane + FULL * 32;
        if (i < N4) {
            float4 a = __ldcs(wr + i); float4 b = xs[i];
            acc += a.x * b.x + a.y * b.y + a.z * b.z + a.w * b.w;
        }
    }
#pragma unroll
    for (int o = 16; o; o >>= 1) acc += __shfl_xor_sync(0xffffffffu, acc, o);
    return acc;
}

template<int N4>
__device__ __forceinline__ void quad_dot_s(const float4* __restrict__ W0,
                                           const float4* __restrict__ W1,
                                           const float4* __restrict__ W2,
                                           const float4* __restrict__ W3,
                                           const float4* __restrict__ xs, int lane,
                                           float& a0, float& a1, float& a2, float& a3) {
    a0 = a1 = a2 = a3 = 0.f;
    constexpr int FULL = N4 / 32;
#pragma unroll 2
    for (int k = 0; k < FULL; k++) {
        int i = lane + k * 32;
        float4 x = xs[i];
        float4 q0 = __ldcs(W0 + i), q1 = __ldcs(W1 + i);
        float4 q2 = __ldcs(W2 + i), q3 = __ldcs(W3 + i);
        a0 += q0.x * x.x + q0.y * x.y + q0.z * x.z + q0.w * x.w;
        a1 += q1.x * x.x + q1.y * x.y + q1.z * x.z + q1.w * x.w;
        a2 += q2.x * x.x + q2.y * x.y + q2.z * x.z + q2.w * x.w;
        a3 += q3.x * x.x + q3.y * x.y + q3.z * x.z + q3.w * x.w;
    }
    if constexpr (N4 % 32 != 0) {
        int i = lane + FULL * 32;
        if (i < N4) {
            float4 x = xs[i];
            float4 q0 = __ldcs(W0 + i), q1 = __ldcs(W1 + i);
            float4 q2 = __ldcs(W2 + i), q3 = __ldcs(W3 + i);
            a0 += q0.x * x.x + q0.y * x.y + q0.z * x.z + q0.w * x.w;
            a1 += q1.x * x.x + q1.y * x.y + q1.z * x.z + q1.w * x.w;
            a2 += q2.x * x.x + q2.y * x.y + q2.z * x.z + q2.w * x.w;
            a3 += q3.x * x.x + q3.y * x.y + q3.z * x.z + q3.w * x.w;
        }
    }
#pragma unroll
    for (int o = 16; o; o >>= 1) {
        a0 += __shfl_xor_sync(0xffffffffu, a0, o);
        a1 += __shfl_xor_sync(0xffffffffu, a1, o);
        a2 += __shfl_xor_sync(0xffffffffu, a2, o);
        a3 += __shfl_xor_sync(0xffffffffu, a3, o);
    }
}

// --------------------------------------------------------------------------
__global__ void __launch_bounds__(NTHREADS, 1) fused_decoder(
    const int* __restrict__ tok, const float* __restrict__ hid,
    const float* __restrict__ enc, const float* __restrict__ nlg,
    const float* __restrict__ emb, const float* __restrict__ attn_W,
    const float* __restrict__ comb_W, const float* __restrict__ comb_b,
    const float* __restrict__ fc1_W, const float* __restrict__ fc1_b,
    const float* __restrict__ fc2_W, const float* __restrict__ fc2_b,
    const float* __restrict__ Wih, const float* __restrict__ Whh,
    const float* __restrict__ bih, const float* __restrict__ bhh,
    const float* __restrict__ out_W, const float* __restrict__ out_b,
    float* __restrict__ out)
{
    __shared__ __align__(16) float sx[2608];
    __shared__ float sr[64];
    __shared__ float swt[64];
    __shared__ float sp[32];
    __shared__ int sc_chunk;
    const int b = blockIdx.x, tid = threadIdx.x;
    const int w = tid >> 5, lane = tid & 31;

    if (b < CHAIN_NB) {
        // ======================= CHAIN (64 blocks) =========================
        // S0: v-partials: 32 k-chunks (32 rows of attn_W; H=1024 total)
        //     x 2 column halves -> 64 blocks
        {
            int kc = b >> 1, half = b & 1;
            if (tid < 32) sx[tid] = hid[kc * 32 + tid];
            __syncthreads();
            int col = half * 1024 + tid;
            const float* Wp = attn_W + (size_t)(kc * 32) * TWO_H + col;
            float acc = 0.f;
#pragma unroll 8
            for (int kk = 0; kk < 32; ++kk)
                acc = fmaf(Wp[(size_t)kk * TWO_H], sx[kk], acc);
            g_vpart[kc * 2048 + col] = acc;
        }
        gbar(0, CHAIN_NB);

        // S1: score logits = enc . v   (sum the 32 v-partials first)
        {
            __syncthreads();
            for (int i = tid; i < 2048; i += NTHREADS) {
                float s = 0.f;
#pragma unroll
                for (int k = 0; k < 32; k++) s += g_vpart[k * 2048 + i];
                sx[i] = s;
            }
            __syncthreads();
            int row = b * 32 + w;
            float acc = wdot<TWO_H / 4>((const float4*)(enc + (size_t)row * TWO_H),
                                        (const float4*)sx, lane);
            if (lane == 0) g_scores[row] = acc;
        }
        gbar(1, CHAIN_NB);

        // S2: per-block softmax (redundant, deterministic) + ctx partials
        {
            float l0 = g_scores[tid], l1 = g_scores[tid + 1024];
            float m = fmaxf(l0, l1);
#pragma unroll
            for (int o = 16; o; o >>= 1) m = fmaxf(m, __shfl_xor_sync(0xffffffffu, m, o));
            if (lane == 0) sr[w] = m;
            __syncthreads();
            if (tid == 0) { float v = sr[0]; for (int k = 1; k < 32; k++) v = fmaxf(v, sr[k]); sr[32] = v; }
            __syncthreads();
            float M = sr[32];
            float e = expf(l0 - M) + expf(l1 - M);
#pragma unroll
            for (int o = 16; o; o >>= 1) e += __shfl_xor_sync(0xffffffffu, e, o);
            if (lane == 0) sr[w] = e;
            __syncthreads();
            if (tid == 0) { float v = 0.f; for (int k = 0; k < 32; k++) v += sr[k]; sr[33] = v; }
            __syncthreads();
            float invZ = 1.f / sr[33];
            if (b == 0) {   // attention-weights output
                out[VOCAB + H + tid]        = expf(l0 - M) * invZ;
                out[VOCAB + H + 1024 + tid] = expf(l1 - M) * invZ;
            }
            // ctx partials: kc-th 64-row chunk of scores (S_LEN=2048 -> 32 chunks)
            int kc = b >> 1, half = b & 1;
            if (tid < 64) swt[tid] = expf(g_scores[kc * 64 + tid] - M) * invZ;
            __syncthreads();
            int col = half * 1024 + tid;
            const float* Ep = enc + (size_t)(kc * 64) * TWO_H + col;
            float acc = 0.f;
#pragma unroll 8
            for (int rr = 0; rr < 64; ++rr)
                acc = fmaf(Ep[(size_t)rr * TWO_H], swt[rr], acc);
            g_ctxpart[kc * 2048 + col] = acc;
        }
        gbar(2, CHAIN_NB);

        // S3: comb — 64 blocks, 16 rows each, 2 warps per row (K-split)
        {
            int t = *tok;
            __syncthreads();
            for (int i = tid; i < COMB_IN; i += NTHREADS) {
                float v;
                if (i < D_EMB) v = emb[(size_t)t * D_EMB + i];
                else if (i < D_EMB + TWO_H) {
                    int c = i - D_EMB; float s = 0.f;
#pragma unroll
                    for (int k = 0; k < 32; k++) s += g_ctxpart[k * 2048 + c];
                    v = s;
                } else v = nlg[i - (D_EMB + TWO_H)];
                sx[i] = v;
            }
            __syncthreads();
            int row = b * 16 + (w >> 1), half = w & 1;
            float part = wdot<COMB_IN / 8>(
                (const float4*)(comb_W + (size_t)row * COMB_IN + half * (COMB_IN / 2)),
                (const float4*)(sx + half * (COMB_IN / 2)), lane);
            if (lane == 0) sp[w] = part;
            __syncthreads();
            if (tid < 16) {
                int r = b * 16 + tid;
                g_x1[r] = fmaxf(sp[2 * tid] + sp[2 * tid + 1] + comb_b[r], 0.f);
            }
        }
        gbar(3, CHAIN_NB);

        // S4: fc1 — 64 blocks, 16 rows, 2-warp split
        {
            for (int i = tid; i < H; i += NTHREADS) sx[i] = g_x1[i];
            __syncthreads();
            int row = b * 16 + (w >> 1), half = w & 1;
            float part = wdot<H / 8>(
                (const float4*)(fc1_W + (size_t)row * H + half * (H / 2)),
                (const float4*)(sx + half * (H / 2)), lane);
            if (lane == 0) sp[w] = part;
            __syncthreads();
            if (tid < 16) {
                int r = b * 16 + tid;
                g_x2[r] = fmaxf(sp[2 * tid] + sp[2 * tid + 1] + fc1_b[r], 0.f);
            }
        }
        gbar(4, CHAIN_NB);

        // S5: fc2
        {
            for (int i = tid; i < H; i += NTHREADS) sx[i] = g_x2[i];
            __syncthreads();
            int row = b * 16 + (w >> 1), half = w & 1;
            float part = wdot<H / 8>(
                (const float4*)(fc2_W + (size_t)row * H + half * (H / 2)),
                (const float4*)(sx + half * (H / 2)), lane);
            if (lane == 0) sp[w] = part;
            __syncthreads();
            if (tid < 16) {
                int r = b * 16 + tid;
                g_x3[r] = fmaxf(sp[2 * tid] + sp[2 * tid + 1] + fc2_b[r], 0.f);
            }
        }
        gbar(5, CHAIN_NB);

        // S6: gi = Wih . x3 + bih  (64 blocks, 3072 rows)
        // no trailing chain barrier: the full-grid barrier before phase F
        // orders these writes for the redundant gate computation.
        {
            for (int i = tid; i < H; i += NTHREADS) sx[i] = g_x3[i];
            __syncthreads();
            int gw2 = b * 32 + w;
            for (int r = gw2; r < 3072; r += 2048) {
                float acc = wdot<H / 4>((const float4*)(Wih + (size_t)r * H),
                                        (const float4*)sx, lane);
                if (lane == 0) g_gi[r] = acc + bih[r];
            }
        }
    } else {
        // ============ HELPERS (80 blocks): gh = Whh.h + bhh ================
        for (int i = tid; i < H; i += NTHREADS) sx[i] = hid[i];
        __syncthreads();
        int gw = (b - CHAIN_NB) * 32 + w;   // [0, 2560)
        {
            float acc = wdot<H / 4>((const float4*)(Whh + (size_t)gw * H),
                                    (const float4*)sx, lane);
            if (lane == 0) g_gh[gw] = acc + bhh[gw];
        }
        if (gw < 512) {
            int r2 = gw + 2560;             // rows [2560, 3072)
            float acc = wdot<H / 4>((const float4*)(Whh + (size_t)r2 * H),
                                    (const float4*)sx, lane);
            if (lane == 0) g_gh[r2] = acc + bhh[r2];
        }
    }

    // ============ ALL BLOCKS: const logits via work stealing ===============
    // out[r] = out_b[r] + out_W[r, 1024:1552] . [nlg, emb]
    {
        int t = *tok;
        __syncthreads();
        for (int i = tid; i < CONST_N; i += NTHREADS)
            sx[i] = (i < L_CLS) ? nlg[i] : emb[(size_t)t * D_EMB + (i - L_CLS)];
        __syncthreads();
        for (;;) {
            if (tid == 0) sc_chunk = (int)atomicAdd(&g_wq, 1u);
            __syncthreads();
            int c = sc_chunk;
            __syncthreads();
            if (c * 128 >= VOCAB) break;
            int r0 = c * 128 + w * 4;
            if (r0 >= VOCAB) continue;
            const float* base = out_W + (size_t)r0 * OUT_IN + H;
            if (r0 + 3 < VOCAB) {
                float a0, a1, a2, a3;
                quad_dot_s<CONST_N4>((const float4*)base,
                                     (const float4*)(base + OUT_IN),
                                     (const float4*)(base + 2 * OUT_IN),
                                     (const float4*)(base + 3 * OUT_IN),
                                     (const float4*)sx, lane, a0, a1, a2, a3);
                if (lane < 4) {
                    float acc = (lane == 0) ? a0 : (lane == 1) ? a1 : (lane == 2) ? a2 : a3;
                    out[r0 + lane] = acc + out_b[r0 + lane];
                }
            } else {
                for (int j = 0; j < 4; j++) {
                    int r = r0 + j;
                    if (r >= VOCAB) break;
                    float acc = wdot_s<CONST_N4>((const float4*)(out_W + (size_t)r * OUT_IN + H),
                                                 (const float4*)sx, lane);
                    if (lane == 0) out[r] = acc + out_b[r];
                }
            }
        }
    }

    // ============== FULL GRID: gates (redundant) + h_new logits ============
    gbar(6, NB);
    if (b == 0 && tid == 0) g_wq = 0;  // reset for next replay
    {
        // every block computes h_new element-wise into its own smem
        // (identical fp ops in every block -> deterministic)
        {
            float r = 1.f / (1.f + expf(-(g_gi[tid] + g_gh[tid])));
            float z = 1.f / (1.f + expf(-(g_gi[H + tid] + g_gh[H + tid])));
            float n = tanhf(g_gi[2 * H + tid] + r * g_gh[2 * H + tid]);
            float hn = (1.f - z) * n + z * hid[tid];
            sx[tid] = hn;
            if (b == 0) out[VOCAB + tid] = hn;   // h_new output
        }
        __syncthreads();
        float m = -FLT_MAX, ssum = 0.f;
        for (;;) {
            if (tid == 0) sc_chunk = (int)atomicAdd(&g_wq2, 1u);
            __syncthreads();
            int c = sc_chunk;
            __syncthreads();
            if (c * 64 >= VOCAB) break;
            int r0 = c * 64 + w * 2;
            if (r0 >= VOCAB) continue;
            if (r0 + 1 < VOCAB) {
                const float4* W0 = (const float4*)(out_W + (size_t)r0 * OUT_IN);
                const float4* W1 = (const float4*)(out_W + (size_t)(r0 + 1) * OUT_IN);
                float a0 = 0.f, a1 = 0.f;
#pragma unroll
                for (int k = 0; k < 8; k++) {
                    int i = lane + 32 * k;
                    float4 x = ((const float4*)sx)[i];
                    float4 q0 = __ldcs(W0 + i), q1 = __ldcs(W1 + i);
                    a0 += q0.x * x.x + q0.y * x.y + q0.z * x.z + q0.w * x.w;
                    a1 += q1.x * x.x + q1.y * x.y + q1.z * x.z + q1.w * x.w;
                }
                // pair reduce: lane 0 -> row r0, lane 16 -> row r0+1
                a0 += __shfl_xor_sync(0xffffffffu, a0, 16);
                a1 += __shfl_xor_sync(0xffffffffu, a1, 16);
                float bb = (lane & 16) ? a1 : a0;
                bb += __shfl_xor_sync(0xffffffffu, bb, 8);
                bb += __shfl_xor_sync(0xffffffffu, bb, 4);
                bb += __shfl_xor_sync(0xffffffffu, bb, 2);
                bb += __shfl_xor_sync(0xffffffffu, bb, 1);
                if ((lane & 15) == 0) {
                    int r = r0 + (lane >> 4);
                    float z = out[r] + bb;
                    out[r] = z;
                    if (z > m) { ssum = ssum * expf(m - z) + 1.f; m = z; }
                    else       { ssum += expf(z - m); }
                }
            } else {
                // single remaining row (r0 == VOCAB-1)
                float a = wdot_s<H / 4>((const float4*)(out_W + (size_t)r0 * OUT_IN),
                                        (const float4*)sx, lane);
                if (lane == 0) {
                    float z = out[r0] + a;
                    out[r0] = z;
                    if (z > m) { ssum = ssum * expf(m - z) + 1.f; m = z; }
                    else       { ssum += expf(z - m); }
                }
            }
        }
        // merge (m, ssum) across lanes
#pragma unroll
        for (int o = 16; o; o >>= 1) {
            float mo = __shfl_xor_sync(0xffffffffu, m, o);
            float so = __shfl_xor_sync(0xffffffffu, ssum, o);
            float nm = fmaxf(m, mo);
            ssum = ssum * expf(m - nm) + so * expf(mo - nm);
            m = nm;
        }
        if (lane == 0) { sr[w] = m; sr[32 + w] = ssum; }
        __syncthreads();
        if (tid == 0) {
            float M = -FLT_MAX;
            for (int k = 0; k < 32; k++) M = fmaxf(M, sr[k]);
            float S = 0.f;
            for (int k = 0; k < 32; k++) S += sr[32 + k] * expf(sr[k] - M);
            g_pm[b] = M; g_ps[b] = S;
        }
    }
    gbar(7, NB);
    if (b == 0 && tid == 0) g_wq2 = 0;  // reset for next replay
    // every block computes logZ redundantly (saves one full-grid barrier)
    {
        if (w == 0) {
            float m = -FLT_MAX, s = 0.f;
            for (int i = lane; i < NB; i += 32) {
                float mi = g_pm[i], si = g_ps[i];
                float nm = fmaxf(m, mi);
                s = s * expf(m - nm) + si * expf(mi - nm);
                m = nm;
            }
#pragma unroll
            for (int o = 16; o; o >>= 1) {
                float mo = __shfl_xor_sync(0xffffffffu, m, o);
                float so = __shfl_xor_sync(0xffffffffu, s, o);
                float nm = fmaxf(m, mo);
                s = s * expf(m - nm) + so * expf(mo - nm);
                m = nm;
            }
            if (lane == 0) sr[0] = m + logf(s);
        }
        __syncthreads();
        float lz = sr[0];
        int i = b * NTHREADS + tid;
        if (i < VOCAB) out[i] -= lz;
    }
}

// --------------------------------------------------------------------------
extern "C" void kernel_launch(void* const* d_in, const int* in_sizes, int n_in,
                              void* d_out, int out_size) {
    const int*   tok    = (const int*)d_in[0];
    const float* hid    = (const float*)d_in[1];
    const float* enc    = (const float*)d_in[2];
    const float* nlg    = (const float*)d_in[3];
    const float* emb    = (const float*)d_in[4];
    const float* attn_W = (const float*)d_in[5];
    // d_in[6] = attn_b: softmax-invariant, drops out by construction
    const float* comb_W = (const float*)d_in[7];
    const float* comb_b = (const float*)d_in[8];
    const float* fc1_W  = (const float*)d_in[9];
    const float* fc1_b  = (const float*)d_in[10];
    const float* fc2_W  = (const float*)d_in[11];
    const float* fc2_b  = (const float*)d_in[12];
    const float* Wih    = (const float*)d_in[13];
    const float* Whh    = (const float*)d_in[14];
    const float* bih    = (const float*)d_in[15];
    const float* bhh    = (const float*)d_in[16];
    const float* out_W  = (const float*)d_in[17];
    const float* out_b  = (const float*)d_in[18];
    float* out = (float*)d_out;

    fused_decoder<<<NB, NTHREADS>>>(tok, hid, enc, nlg, emb, attn_W,
                                    comb_W, comb_b, fc1_W, fc1_b, fc2_W, fc2_b,
                                    Wih, Whh, bih, bhh, out_W, out_b, out);
}